// round 10
// baseline (speedup 1.0000x reference)
#include <cuda_runtime.h>
#include <math.h>

// RotationalConv2D: B=4,H=W=128,C=16,F=32,K=5 -> Ho=Wo=124
// Block: 8x8 patch tile (64 patches), 128 threads, grid 16x16x4.
// Rotate: thread=(patch, ch-half) -> rotT[k][patch], double buffered.
// GEMM: each warp covers the WHOLE 64x32 tile for its k-quarter
// (k16 = w, w+4, w+8, w+12). Lane = (pg = lane&7 -> 8 patches, fg = lane>>3
// -> 8 f). Per k: rot 2xLDS.128 (splat per patch), W 2xLDG.128 (ulonglong2
// f-pairs, L1-resident), 32 FFMA2 into acc[8][4] (f32x2 pairs).
// End: cross-warp k-reduction through smem (reused region), then store.

#define FMA2(acc, a, b) asm("fma.rn.f32x2 %0, %1, %2, %0;" : "+l"(acc) : "l"(a), "l"(b))
#define ADD2(d, a, b)   asm("add.rn.f32x2 %0, %1, %2;" : "=l"(d) : "l"(a), "l"(b))
#define SPLAT(p, w)     asm("mov.b64 %0, {%1, %1};" : "=l"(p) : "r"(w))

#define NTHREADS 128
// smem floats (loop layout):
#define SM_PLANES 0        // 4 planes * 144 cells * 4 = 2304
#define SM_CHSUM  2304     // 144
#define SM_COS    2448     // 64
#define SM_SIN    2512     // 64
#define SM_ROT    2576     // 2 * 16*64 = 2048
// reduction overlay (after loop): 3 warps * 32 lanes * 32 ull = 3072 ull = 24576 B
#define SMEM_FLOATS 6144   // 24576 B

__device__ float WkG[12800];   // W transposed: WkG[k*32 + f], k = pos*16 + c

__global__ void prepW_kernel(const float* __restrict__ Wg) {
    int i = blockIdx.x * 256 + threadIdx.x;   // 0..12799
    if (i < 12800) {
        int k = i >> 5;
        int f = i & 31;
        WkG[i] = Wg[f * 400 + k];
    }
}

__global__ __launch_bounds__(NTHREADS)
void rotconv_kernel(const float* __restrict__ in,
                    const float* __restrict__ bias,
                    float* __restrict__ out)
{
    extern __shared__ float smem[];
    float4* planes4 = (float4*)(smem + SM_PLANES);   // [c4*144 + cell]
    float*  chsum   = smem + SM_CHSUM;
    float*  cosS    = smem + SM_COS;
    float*  sinS    = smem + SM_SIN;
    float*  rotT    = smem + SM_ROT;

    const int tid   = threadIdx.x;
    const int w     = tid >> 5;
    const int lane  = tid & 31;
    const int tileX = blockIdx.x;     // 0..15
    const int tileY = blockIdx.y;     // 0..15
    const int img   = blockIdx.z;     // 0..3

    // ---------- Phase 0: load input tile (12x12 cells), plane-major ----------
    {
        const float4* in4 = (const float4*)in;
        #pragma unroll 1
        for (int cell = tid; cell < 144; cell += NTHREADS) {
            int y = cell / 12;
            int x = cell - y * 12;
            int gr = tileY * 8 + y; if (gr > 127) gr = 127;
            int gc = tileX * 8 + x; if (gc > 127) gc = 127;
            const float4* src = in4 + ((img * 128 + gr) * 128 + gc) * 4;
            #pragma unroll
            for (int c4 = 0; c4 < 4; ++c4)
                planes4[c4 * 144 + cell] = src[c4];
        }
    }
    __syncthreads();

    // ---------- Phase 1: per-cell channel sums ----------
    #pragma unroll 1
    for (int cell = tid; cell < 144; cell += NTHREADS) {
        float4 a = planes4[cell], b = planes4[144 + cell],
               c = planes4[288 + cell], d = planes4[432 + cell];
        chsum[cell] = (a.x + a.y + a.z + a.w) + (b.x + b.y + b.z + b.w)
                    + (c.x + c.y + c.z + c.w) + (d.x + d.y + d.z + d.w);
    }
    __syncthreads();

    // ---------- Phase 2: centroid -> angle (one thread per patch) ----------
    if (tid < 64) {
        int pr = tid >> 3, pc = tid & 7;
        float tot = 0.f, sr = 0.f, sc = 0.f;
        #pragma unroll
        for (int yy = 0; yy < 5; ++yy)
            #pragma unroll
            for (int xx = 0; xx < 5; ++xx) {
                float s = chsum[(pr + yy) * 12 + (pc + xx)];
                tot += s; sr += s * (float)yy; sc += s * (float)xx;
            }
        tot += 1e-7f;
        float cr = sr / tot - 2.0f;
        float cc = sc / tot - 2.0f + 1e-7f;
        float si, co;
        sincosf(atan2f(cr, cc), &si, &co);
        cosS[tid] = co;
        sinS[tid] = si;
    }
    __syncthreads();

    // rotate role: patch = tid&63, half h = tid>>6 (k 0-7 or 8-15)
    const int rpatch = tid & 63;
    const int h      = tid >> 6;
    const int rr     = rpatch >> 3;
    const int rc     = rpatch & 7;
    const float co = cosS[rpatch];
    const float si = sinS[rpatch];
    const float scale = 1.0f / (1.0f + 1e-7f);
    const float xoff = (4.0f - (co * 4.0f - si * 4.0f)) * 0.5f;
    const float yoff = (4.0f - (si * 4.0f + co * 4.0f)) * 0.5f;

    // GEMM role: pg = lane&7 (patches pg*8..+7), fg = lane>>3 (f = fg*8..+7)
    const int pg = lane & 7;
    const int fg = lane >> 3;

    unsigned long long acc[8][4];   // [patch i][f-pair j]: {f(2j), f(2j+1)}
    #pragma unroll
    for (int i = 0; i < 8; ++i)
        #pragma unroll
        for (int j = 0; j < 4; ++j) acc[i][j] = 0ULL;

    const ulonglong2* Wk2 = (const ulonglong2*)WkG;

    // ---------- Phase 3: 25 positions ----------
    #pragma unroll 1
    for (int pos = 0; pos < 25; ++pos) {
        const int gy = pos / 5;
        const int gx = pos - gy * 5;
        float* buf = rotT + (pos & 1) * 1024;

        // --- rotate own (patch, k-half) ---
        {
            float sx = (co * (float)gx - si * (float)gy + xoff) * scale;
            float sy = (si * (float)gx + co * (float)gy + yoff) * scale;
            float x0f = floorf(sx), y0f = floorf(sy);
            float wx = sx - x0f, wy = sy - y0f;
            int x0 = (int)x0f, y0 = (int)y0f;
            int x1 = x0 + 1,   y1 = y0 + 1;
            bool vx0 = (x0 >= 0) && (x0 < 5);
            bool vx1 = (x1 >= 0) && (x1 < 5);
            bool vy0 = (y0 >= 0) && (y0 < 5);
            bool vy1 = (y1 >= 0) && (y1 < 5);
            int x0c = x0 < 0 ? 0 : (x0 > 4 ? 4 : x0);
            int x1c = x1 < 0 ? 0 : (x1 > 4 ? 4 : x1);
            int y0c = y0 < 0 ? 0 : (y0 > 4 ? 4 : y0);
            int y1c = y1 < 0 ? 0 : (y1 > 4 ? 4 : y1);
            float w00 = (vx0 && vy0) ? (1.f - wx) * (1.f - wy) : 0.f;
            float w01 = (vx1 && vy0) ? wx * (1.f - wy)         : 0.f;
            float w10 = (vx0 && vy1) ? (1.f - wx) * wy         : 0.f;
            float w11 = (vx1 && vy1) ? wx * wy                 : 0.f;

            int cell00 = (rr + y0c) * 12 + (rc + x0c);
            int cell01 = (rr + y0c) * 12 + (rc + x1c);
            int cell10 = (rr + y1c) * 12 + (rc + x0c);
            int cell11 = (rr + y1c) * 12 + (rc + x1c);

            float* dstb = buf + rpatch;
            #pragma unroll
            for (int c4i = 0; c4i < 2; ++c4i) {
                const int c4 = h * 2 + c4i;
                const float4* pl = planes4 + c4 * 144;
                float4 a = pl[cell00], b = pl[cell01], c = pl[cell10], d = pl[cell11];
                float r0 = fmaf(a.x, w00, fmaf(b.x, w01, fmaf(c.x, w10, d.x * w11)));
                float r1 = fmaf(a.y, w00, fmaf(b.y, w01, fmaf(c.y, w10, d.y * w11)));
                float r2 = fmaf(a.z, w00, fmaf(b.z, w01, fmaf(c.z, w10, d.z * w11)));
                float r3 = fmaf(a.w, w00, fmaf(b.w, w01, fmaf(c.w, w10, d.w * w11)));
                dstb[(c4 * 4 + 0) * 64] = r0;
                dstb[(c4 * 4 + 1) * 64] = r1;
                dstb[(c4 * 4 + 2) * 64] = r2;
                dstb[(c4 * 4 + 3) * 64] = r3;
            }
        }
        __syncthreads();

        // --- GEMM: this warp's 4 k-values (k16 = w + 4j) ---
        #pragma unroll
        for (int j = 0; j < 4; ++j) {
            const int k16 = w + 4 * j;
            const float4* rp = (const float4*)(buf + k16 * 64 + pg * 8);
            float4 ra = rp[0], rb = rp[1];
            unsigned long long s0, s1, s2, s3, s4, s5, s6, s7;
            SPLAT(s0, __float_as_uint(ra.x)); SPLAT(s1, __float_as_uint(ra.y));
            SPLAT(s2, __float_as_uint(ra.z)); SPLAT(s3, __float_as_uint(ra.w));
            SPLAT(s4, __float_as_uint(rb.x)); SPLAT(s5, __float_as_uint(rb.y));
            SPLAT(s6, __float_as_uint(rb.z)); SPLAT(s7, __float_as_uint(rb.w));
            const int widx = (pos * 16 + k16) * 16 + fg * 4;   // ull units
            ulonglong2 wA = Wk2[widx >> 1];
            ulonglong2 wB = Wk2[(widx >> 1) + 1];
            FMA2(acc[0][0], s0, wA.x); FMA2(acc[0][1], s0, wA.y);
            FMA2(acc[0][2], s0, wB.x); FMA2(acc[0][3], s0, wB.y);
            FMA2(acc[1][0], s1, wA.x); FMA2(acc[1][1], s1, wA.y);
            FMA2(acc[1][2], s1, wB.x); FMA2(acc[1][3], s1, wB.y);
            FMA2(acc[2][0], s2, wA.x); FMA2(acc[2][1], s2, wA.y);
            FMA2(acc[2][2], s2, wB.x); FMA2(acc[2][3], s2, wB.y);
            FMA2(acc[3][0], s3, wA.x); FMA2(acc[3][1], s3, wA.y);
            FMA2(acc[3][2], s3, wB.x); FMA2(acc[3][3], s3, wB.y);
            FMA2(acc[4][0], s4, wA.x); FMA2(acc[4][1], s4, wA.y);
            FMA2(acc[4][2], s4, wB.x); FMA2(acc[4][3], s4, wB.y);
            FMA2(acc[5][0], s5, wA.x); FMA2(acc[5][1], s5, wA.y);
            FMA2(acc[5][2], s5, wB.x); FMA2(acc[5][3], s5, wB.y);
            FMA2(acc[6][0], s6, wA.x); FMA2(acc[6][1], s6, wA.y);
            FMA2(acc[6][2], s6, wB.x); FMA2(acc[6][3], s6, wB.y);
            FMA2(acc[7][0], s7, wA.x); FMA2(acc[7][1], s7, wA.y);
            FMA2(acc[7][2], s7, wB.x); FMA2(acc[7][3], s7, wB.y);
        }
        // next rotate writes the other rotT buffer; pos+1 barrier orders this
        // GEMM's reads before pos+2 overwrites. One barrier per position.
    }

    // ---------- Phase 4: cross-warp k-reduction + store ----------
    __syncthreads();   // all GEMM reads of rotT/planes done; reuse smem
    unsigned long long* red = (unsigned long long*)smem;   // [3][32 ull][32 lanes]

    if (w > 0) {
        unsigned long long* rb = red + (w - 1) * 1024;
        #pragma unroll
        for (int t = 0; t < 32; ++t)
            rb[t * 32 + lane] = acc[t >> 2][t & 3];
    }
    __syncthreads();

    if (w == 0) {
        #pragma unroll
        for (int t = 0; t < 32; ++t) {
            unsigned long long v = acc[t >> 2][t & 3];
            ADD2(v, v, red[t * 32 + lane]);
            ADD2(v, v, red[1024 + t * 32 + lane]);
            ADD2(v, v, red[2048 + t * 32 + lane]);
            acc[t >> 2][t & 3] = v;
        }
        const float4* bias4 = (const float4*)bias;
        float4 bv0 = bias4[fg * 2];
        float4 bv1 = bias4[fg * 2 + 1];
        const int oh = tileY * 8 + pg;
        union { unsigned long long u; float2 f; } u0, u1, u2, u3;
        if (oh < 124) {
            #pragma unroll
            for (int i = 0; i < 8; ++i) {
                int ow = tileX * 8 + i;
                if (ow < 124) {
                    u0.u = acc[i][0]; u1.u = acc[i][1];
                    u2.u = acc[i][2]; u3.u = acc[i][3];
                    float4* ob = (float4*)(out + ((size_t)((img * 124 + oh) * 124 + ow)) * 32)
                                 + fg * 2;
                    ob[0] = make_float4(u0.f.x + bv0.x, u0.f.y + bv0.y,
                                        u1.f.x + bv0.z, u1.f.y + bv0.w);
                    ob[1] = make_float4(u2.f.x + bv1.x, u2.f.y + bv1.y,
                                        u3.f.x + bv1.z, u3.f.y + bv1.w);
                }
            }
        }
    }
}

extern "C" void kernel_launch(void* const* d_in, const int* in_sizes, int n_in,
                              void* d_out, int out_size)
{
    const float* in   = (const float*)d_in[0];   // [4,128,128,16]
    const float* Wg   = (const float*)d_in[1];   // [32,5,5,16]
    const float* bias = (const float*)d_in[2];   // [32]
    float* out = (float*)d_out;                  // [4,124,124,32]

    prepW_kernel<<<50, 256>>>(Wg);

    const int smem_bytes = SMEM_FLOATS * (int)sizeof(float);   // 24576
    cudaFuncSetAttribute(rotconv_kernel,
                         cudaFuncAttributeMaxDynamicSharedMemorySize, smem_bytes);
    dim3 grid(16, 16, 4);
    rotconv_kernel<<<grid, NTHREADS, smem_bytes>>>(in, bias, out);
}

// round 11
// speedup vs baseline: 1.1696x; 1.1696x over previous
#include <cuda_runtime.h>
#include <math.h>

// RotationalConv2D: B=4,H=W=128,C=16,F=32,K=5 -> Ho=Wo=124
// Thread = one patch, owns all 32 output features (16 f32x2 acc pairs).
// Rotate in registers -> FFMA2 immediately; W in __constant__ (uniform port,
// zero L1 wavefronts). No smem traffic in the main loop except the bilinear
// gather from the input-tile planes. No __syncthreads after the prologue.

#define FMA2(acc, a, b) asm("fma.rn.f32x2 %0, %1, %2, %0;" : "+l"(acc) : "l"(a), "l"(b))
#define MUL2(d, a, b)   asm("mul.rn.f32x2 %0, %1, %2;" : "=l"(d) : "l"(a), "l"(b))
#define SPLAT(p, w)     asm("mov.b64 %0, {%1, %1};" : "=l"(p) : "r"(w))
#define UNPACK(lo, hi, p) asm("mov.b64 {%0, %1}, %2;" : "=r"(lo), "=r"(hi) : "l"(p))

#define NTHREADS 128
#define ITX 20              // tile 16 wide + 4
#define ITY 12              // tile 8 tall + 4
#define NCELL 240
// smem floats: planes4 [4][240] float4 = 3840 | chsum 240
#define SMEM_FLOATS 4080    // 16320 B

__constant__ ulonglong2 Wc2[3200];   // [k=400][fp2=8], each = {{f0,f1},{f2,f3}}

__device__ float WkT[12800];         // staging: [k][f]

__global__ void prepW_kernel(const float* __restrict__ Wg) {
    int i = blockIdx.x * 256 + threadIdx.x;
    if (i < 12800) {
        int k = i >> 5, f = i & 31;
        WkT[k * 32 + f] = Wg[f * 400 + k];
    }
}

union F4U2 { float4 f4; ulonglong2 u2; };

__global__ __launch_bounds__(NTHREADS)
void rotconv_kernel(const float* __restrict__ in,
                    const float* __restrict__ bias,
                    float* __restrict__ out)
{
    extern __shared__ float smem[];
    float4* planes4 = (float4*)smem;        // [c4*240 + cell]
    float*  chsum   = smem + 3840;

    const int tid   = threadIdx.x;
    const int mr    = tid >> 4;     // 0..7
    const int mc    = tid & 15;     // 0..15
    const int tileX = blockIdx.x;   // 0..7  (16 wide)
    const int tileY = blockIdx.y;   // 0..15 (8 tall)
    const int img   = blockIdx.z;

    // ---------- Phase 0: load input tile (20x12 cells), plane-major ----------
    {
        const float4* in4 = (const float4*)in;
        #pragma unroll 1
        for (int cell = tid; cell < NCELL; cell += NTHREADS) {
            int y = cell / ITX;
            int x = cell - y * ITX;
            int gr = tileY * 8 + y;  if (gr > 127) gr = 127;
            int gc = tileX * 16 + x; if (gc > 127) gc = 127;
            const float4* src = in4 + ((img * 128 + gr) * 128 + gc) * 4;
            #pragma unroll
            for (int c4 = 0; c4 < 4; ++c4)
                planes4[c4 * NCELL + cell] = src[c4];
        }
    }
    __syncthreads();

    // ---------- Phase 1: per-cell channel sums ----------
    #pragma unroll 1
    for (int cell = tid; cell < NCELL; cell += NTHREADS) {
        float4 a = planes4[cell], b = planes4[NCELL + cell],
               c = planes4[2 * NCELL + cell], d = planes4[3 * NCELL + cell];
        chsum[cell] = (a.x + a.y + a.z + a.w) + (b.x + b.y + b.z + b.w)
                    + (c.x + c.y + c.z + c.w) + (d.x + d.y + d.z + d.w);
    }
    __syncthreads();

    // ---------- Phase 2: centroid -> angle (own patch) ----------
    float co, si;
    {
        float tot = 0.f, sr = 0.f, sc = 0.f;
        #pragma unroll
        for (int yy = 0; yy < 5; ++yy)
            #pragma unroll
            for (int xx = 0; xx < 5; ++xx) {
                float s = chsum[(mr + yy) * ITX + (mc + xx)];
                tot += s; sr += s * (float)yy; sc += s * (float)xx;
            }
        tot += 1e-7f;
        float cr = sr / tot - 2.0f;
        float cc = sc / tot - 2.0f + 1e-7f;
        sincosf(atan2f(cr, cc), &si, &co);
    }

    const float scale = 1.0f / (1.0f + 1e-7f);
    const float xoff = (4.0f - (co * 4.0f - si * 4.0f)) * 0.5f;
    const float yoff = (4.0f - (si * 4.0f + co * 4.0f)) * 0.5f;

    unsigned long long acc[16];     // acc[fp] = {f(2fp), f(2fp+1)}
    #pragma unroll
    for (int j = 0; j < 16; ++j) acc[j] = 0ULL;

    // ---------- Phase 3: 25 positions, fully register-resident ----------
    #pragma unroll 1
    for (int pos = 0; pos < 25; ++pos) {
        const int gy = pos / 5;
        const int gx = pos - gy * 5;

        float sx = (co * (float)gx - si * (float)gy + xoff) * scale;
        float sy = (si * (float)gx + co * (float)gy + yoff) * scale;
        float x0f = floorf(sx), y0f = floorf(sy);
        float wx = sx - x0f, wy = sy - y0f;
        int x0 = (int)x0f, y0 = (int)y0f;
        int x1 = x0 + 1,   y1 = y0 + 1;
        bool vx0 = (x0 >= 0) && (x0 < 5);
        bool vx1 = (x1 >= 0) && (x1 < 5);
        bool vy0 = (y0 >= 0) && (y0 < 5);
        bool vy1 = (y1 >= 0) && (y1 < 5);
        int x0c = x0 < 0 ? 0 : (x0 > 4 ? 4 : x0);
        int x1c = x1 < 0 ? 0 : (x1 > 4 ? 4 : x1);
        int y0c = y0 < 0 ? 0 : (y0 > 4 ? 4 : y0);
        int y1c = y1 < 0 ? 0 : (y1 > 4 ? 4 : y1);
        float w00 = (vx0 && vy0) ? (1.f - wx) * (1.f - wy) : 0.f;
        float w01 = (vx1 && vy0) ? wx * (1.f - wy)         : 0.f;
        float w10 = (vx0 && vy1) ? (1.f - wx) * wy         : 0.f;
        float w11 = (vx1 && vy1) ? wx * wy                 : 0.f;

        unsigned long long s00, s01, s10, s11;
        SPLAT(s00, __float_as_uint(w00));
        SPLAT(s01, __float_as_uint(w01));
        SPLAT(s10, __float_as_uint(w10));
        SPLAT(s11, __float_as_uint(w11));

        const int cell00 = (mr + y0c) * ITX + (mc + x0c);
        const int cell01 = (mr + y0c) * ITX + (mc + x1c);
        const int cell10 = (mr + y1c) * ITX + (mc + x0c);
        const int cell11 = (mr + y1c) * ITX + (mc + x1c);

        const ulonglong2* Wrow = Wc2 + pos * 128;   // 16 ch * 8 pairs

        #pragma unroll
        for (int q = 0; q < 4; ++q) {               // channel quad
            const float4* pl = planes4 + q * NCELL;
            F4U2 a, b, c, d;
            a.f4 = pl[cell00];
            b.f4 = pl[cell01];
            c.f4 = pl[cell10];
            d.f4 = pl[cell11];

            unsigned long long r01, r23;            // rot ch pairs
            MUL2(r01, a.u2.x, s00);
            FMA2(r01, b.u2.x, s01);
            FMA2(r01, c.u2.x, s10);
            FMA2(r01, d.u2.x, s11);
            MUL2(r23, a.u2.y, s00);
            FMA2(r23, b.u2.y, s01);
            FMA2(r23, c.u2.y, s10);
            FMA2(r23, d.u2.y, s11);

            unsigned v0, v1, v2, v3;
            UNPACK(v0, v1, r01);
            UNPACK(v2, v3, r23);
            unsigned long long sv;
            const ulonglong2* Wq = Wrow + q * 32;

            SPLAT(sv, v0);
            #pragma unroll
            for (int j = 0; j < 8; ++j) {
                ulonglong2 wp = Wq[j];
                FMA2(acc[2 * j],     sv, wp.x);
                FMA2(acc[2 * j + 1], sv, wp.y);
            }
            SPLAT(sv, v1);
            #pragma unroll
            for (int j = 0; j < 8; ++j) {
                ulonglong2 wp = Wq[8 + j];
                FMA2(acc[2 * j],     sv, wp.x);
                FMA2(acc[2 * j + 1], sv, wp.y);
            }
            SPLAT(sv, v2);
            #pragma unroll
            for (int j = 0; j < 8; ++j) {
                ulonglong2 wp = Wq[16 + j];
                FMA2(acc[2 * j],     sv, wp.x);
                FMA2(acc[2 * j + 1], sv, wp.y);
            }
            SPLAT(sv, v3);
            #pragma unroll
            for (int j = 0; j < 8; ++j) {
                ulonglong2 wp = Wq[24 + j];
                FMA2(acc[2 * j],     sv, wp.x);
                FMA2(acc[2 * j + 1], sv, wp.y);
            }
        }
    }

    // ---------- Phase 4: write out (own patch, 32 f) ----------
    {
        const int oh = tileY * 8 + mr;
        const int ow = tileX * 16 + mc;
        if (oh < 124 && ow < 124) {
            float4* ob = (float4*)(out + ((size_t)((img * 124 + oh) * 124 + ow)) * 32);
            const float4* b4 = (const float4*)bias;
            union { unsigned long long u; float2 f; } p0, p1;
            #pragma unroll
            for (int j = 0; j < 8; ++j) {
                float4 bv = b4[j];
                p0.u = acc[2 * j];
                p1.u = acc[2 * j + 1];
                ob[j] = make_float4(p0.f.x + bv.x, p0.f.y + bv.y,
                                    p1.f.x + bv.z, p1.f.y + bv.w);
            }
        }
    }
}

extern "C" void kernel_launch(void* const* d_in, const int* in_sizes, int n_in,
                              void* d_out, int out_size)
{
    const float* in   = (const float*)d_in[0];   // [4,128,128,16]
    const float* Wg   = (const float*)d_in[1];   // [32,5,5,16]
    const float* bias = (const float*)d_in[2];   // [32]
    float* out = (float*)d_out;                  // [4,124,124,32]

    prepW_kernel<<<50, 256>>>(Wg);

    void* wsrc = nullptr;
    cudaGetSymbolAddress(&wsrc, WkT);
    cudaMemcpyToSymbolAsync(Wc2, wsrc, 12800 * sizeof(float), 0,
                            cudaMemcpyDeviceToDevice, 0);

    const int smem_bytes = SMEM_FLOATS * (int)sizeof(float);   // 16320
    cudaFuncSetAttribute(rotconv_kernel,
                         cudaFuncAttributeMaxDynamicSharedMemorySize, smem_bytes);
    dim3 grid(8, 16, 4);
    rotconv_kernel<<<grid, NTHREADS, smem_bytes>>>(in, bias, out);
}